// round 13
// baseline (speedup 1.0000x reference)
#include <cuda_runtime.h>
#include <cuda_bf16.h>
#include <math.h>

// PMSN / S4D:  out[h,l] = Re( sum_n coeff_{h,n} * A_bar_{h,n}^l )
//
// R13: warp-autonomous. Each warp handles half an h-row; no smem, no
// __syncthreads. Each lane computes ONE MUFU cexp "job"; the power table is
// then gathered via __shfl_sync. 8 order-2 real recurrence chains per thread
// (2 conjugate-reduced states x 4 adjacent l), float4 stores, stride 128.
//
// Lane job map (s = lane>>4 in {0,1} = active state, r = lane&15):
//   r=0..3  : P32[r]  = A_bar^(32r)      (r=0 -> m=0 -> exactly 1+0i)
//   r=4..11 : P4[r-4] = A_bar^(4(r-4))
//   r=12    : Ab      = A_bar
//   r=13    : W       = A_bar^128
//   r=14    : Ahalf   = A_bar^(L/2)      (warp-1 seed offset)
//   r=15    : coeff   = 2 * C * B_bar    (pair-doubled)

#define NSTATE 4
#define TPB    256
#define WSTRIDE 128          // l-advance per iteration (32 lanes * 4)

struct __align__(8) cfloat { float r, i; };

__device__ __forceinline__ cfloat cmul(cfloat a, cfloat b) {
    cfloat o;
    o.r = fmaf(a.r, b.r, -a.i * b.i);
    o.i = fmaf(a.r, b.i,  a.i * b.r);
    return o;
}

__device__ __forceinline__ cfloat cshfl(cfloat v, int src) {
    cfloat o;
    o.r = __shfl_sync(0xffffffffu, v.r, src);
    o.i = __shfl_sync(0xffffffffu, v.i, src);
    return o;
}

// exp((a + i b) * m). MUFU + fp32 Cody-Waite phase reduction.
__device__ __forceinline__ cfloat cexp_fast(float a, float b, float m) {
    const float INV2PI = 0.15915494309189535f;
    const float C1     = 6.28125f;                  // exact in fp32
    const float C2     = 1.9353071795864764e-3f;    // 2*pi - C1
    float am = a * m;
    float bm = b * m;
    float k  = rintf(bm * INV2PI);
    float r  = fmaf(-k, C1, bm);
    r        = fmaf(-k, C2, r);
    float s, c;
    __sincosf(r, &s, &c);
    float e = __expf(am);
    cfloat o; o.r = e * c; o.i = e * s;
    return o;
}

__global__ __launch_bounds__(TPB, 8)
void pmsn_kernel(const float* __restrict__ log_dt,
                 const float* __restrict__ log_A_real,
                 const float* __restrict__ A_imag,
                 const float* __restrict__ VinvB_real,
                 const float* __restrict__ VinvB_imag,
                 const float* __restrict__ CV_real,
                 const float* __restrict__ CV_imag,
                 float* __restrict__ out,
                 int H, int L)
{
    const int wp   = threadIdx.x >> 5;
    const int lane = threadIdx.x & 31;
    const int g    = blockIdx.x * (TPB / 32) + wp;   // global warp id
    const int h    = g >> 1;
    const int w    = g & 1;                          // half-row index
    if (h >= H) return;

    const int Lh   = L >> 1;                         // half-row length
    const int base = h * NSTATE;
    const int s    = lane >> 4;                      // which active state's job
    const int r    = lane & 15;                      // job within state

    // ---- pick the s-th state with positive imaginary part ----
    int n = 0;
    {
        int want = s, seen = 0;
#pragma unroll
        for (int m = 0; m < NSTATE; ++m) {
            if (A_imag[base + m] > 0.0f) {
                if (seen == want) n = m;
                ++seen;
            }
        }
    }
    const int idx = base + n;

    const float dt  = __expf(log_dt[h]);
    const float Aim = A_imag[idx];
    const float Are = -__expf(log_A_real[idx]);
    const float a = Are * dt;
    const float b = Aim * dt;

    // ---- one cexp job per lane ----
    float m_exp;
    if      (r < 4)   m_exp = (float)(32 * r);
    else if (r < 12)  m_exp = (float)(4 * (r - 4));
    else if (r == 12) m_exp = 1.0f;
    else if (r == 13) m_exp = (float)WSTRIDE;
    else if (r == 14) m_exp = (float)Lh;
    else              m_exp = 1.0f;                  // Ab for coeff lane

    cfloat myjob = cexp_fast(a, b, m_exp);

    if (r == 15) {
        // coeff = 2 * C * B_bar,  B_bar = (A_bar - 1) * B / A
        const cfloat Ab = myjob;
        const float Br = VinvB_real[idx], Bi = VinvB_imag[idx];
        const float t1r = (Ab.r - 1.0f) * Br - Ab.i * Bi;
        const float t1i = (Ab.r - 1.0f) * Bi + Ab.i * Br;
        const float invA = 1.0f / (Are * Are + Aim * Aim);
        const float Bbr = (t1r * Are + t1i * Aim) * invA;
        const float Bbi = (t1i * Are - t1r * Aim) * invA;
        const float Cr = CV_real[idx], Ci = CV_imag[idx];
        myjob.r = 2.0f * (Cr * Bbr - Ci * Bbi);
        myjob.i = 2.0f * (Cr * Bbi + Ci * Bbr);
    }

    // ---- gather table entries via shuffle; build seeds ----
    const int j4 = lane >> 3;            // 4*lane = 32*j + 4*i
    const int i4 = lane & 7;

    float ua[2][4], ub[2][4], p[2], q[2];

#pragma unroll
    for (int ss = 0; ss < 2; ++ss) {
        const int sb = ss << 4;
        const cfloat P32   = cshfl(myjob, sb + j4);
        const cfloat P4    = cshfl(myjob, sb + 4 + i4);
        const cfloat Ab    = cshfl(myjob, sb + 12);
        const cfloat W     = cshfl(myjob, sb + 13);
        const cfloat Ahalf = cshfl(myjob, sb + 14);
        const cfloat cf    = cshfl(myjob, sb + 15);

        // seed offset for warp half: w ? Ahalf : 1
        cfloat off;
        off.r = w ? Ahalf.r : 1.0f;
        off.i = w ? Ahalf.i : 0.0f;

        cfloat z = cmul(cmul(cmul(cf, off), P32), P4);
#pragma unroll
        for (int o = 0; o < 4; ++o) {
            if (o > 0) z = cmul(z, Ab);
            ua[ss][o] = z.r;
            ub[ss][o] = fmaf(z.r, W.r, -z.i * W.i);
        }
        p[ss] = 2.0f * W.r;
        q[ss] = -fmaf(W.r, W.r, W.i * W.i);
    }

    // ---- main loop: 8 chains, float4 stores, stride 128 within half-row ----
    const int lstart = w * Lh + 4 * lane;
    const int lend   = w * Lh + Lh;
    float* rowp = out + (size_t)h * (size_t)L + lstart;

#pragma unroll 8
    for (int l = lstart; l < lend; l += WSTRIDE) {
        float4 v;
        v.x = ua[0][0] + ua[1][0];
        v.y = ua[0][1] + ua[1][1];
        v.z = ua[0][2] + ua[1][2];
        v.w = ua[0][3] + ua[1][3];
        if (l + 4 <= lend) {
            *reinterpret_cast<float4*>(rowp) = v;
        } else {
            const float vv[4] = {v.x, v.y, v.z, v.w};
            for (int o = 0; o < 4 && l + o < lend; ++o) rowp[o] = vv[o];
        }
        rowp += WSTRIDE;
#pragma unroll
        for (int ss = 0; ss < 2; ++ss)
#pragma unroll
            for (int o = 0; o < 4; ++o) {
                const float x = fmaf(p[ss], ub[ss][o], q[ss] * ua[ss][o]);
                ua[ss][o] = ub[ss][o];
                ub[ss][o] = x;
            }
    }
}

extern "C" void kernel_launch(void* const* d_in, const int* in_sizes, int n_in,
                              void* d_out, int out_size)
{
    const float* log_dt     = (const float*)d_in[0];
    const float* log_A_real = (const float*)d_in[1];
    const float* A_imag     = (const float*)d_in[2];
    const float* VinvB_real = (const float*)d_in[3];
    const float* VinvB_imag = (const float*)d_in[4];
    const float* CV_real    = (const float*)d_in[5];
    const float* CV_imag    = (const float*)d_in[6];

    const int H = in_sizes[0];
    const int L = out_size / H;

    float* out = (float*)d_out;

    const int warps  = 2 * H;                  // 2 warps per h-row
    const int blocks = (warps * 32 + TPB - 1) / TPB;
    pmsn_kernel<<<blocks, TPB>>>(log_dt, log_A_real, A_imag,
                                 VinvB_real, VinvB_imag,
                                 CV_real, CV_imag, out, H, L);
}

// round 15
// speedup vs baseline: 1.0516x; 1.0516x over previous
#include <cuda_runtime.h>
#include <cuda_bf16.h>
#include <math.h>

// PMSN / S4D:  out[h,l] = Re( sum_n coeff_{h,n} * A_bar_{h,n}^l )
//
// R14: two kernels, both massively parallel.
//   Pre:  one thread per table entry (H x 2 states x 27 entries). Writes
//         P32[16]=A_bar^(32j), P4[8]=A_bar^(4i), Ab, W=A_bar^512, coeff
//         (=2*C*B_bar, conjugate-pair doubled) to __device__ scratch.
//   Main: 2048 x 128, no smem/sync/divergence. Thread t: seeds
//         z = coeff*P32[t>>3]*P4[t&7] (l = 4t), offsets via Ab; then 8
//         order-2 real recurrence chains (2 states x 4 offsets), STG.128,
//         stride 512, 8 iterations.  u_{k+2} = p u_{k+1} + q u_k,
//         p = 2 Re W, q = -|W|^2.

#define NSTATE 4
#define TPB    128
#define STRIDE (4 * TPB)     // 512
#define HMAX   4096
#define TABN   32            // padded entries per (h,s)

// table layout per (h,s): [0..15]=P32, [16..23]=P4, [24]=Ab, [25]=W, [26]=coeff
__device__ float2 g_tab[HMAX * 2 * TABN];

struct __align__(8) cfloat { float r, i; };

__device__ __forceinline__ cfloat cmul(cfloat a, cfloat b) {
    cfloat o;
    o.r = fmaf(a.r, b.r, -a.i * b.i);
    o.i = fmaf(a.r, b.i,  a.i * b.r);
    return o;
}

// exp((a + i b) * m). MUFU + fp32 Cody-Waite phase reduction.
__device__ __forceinline__ cfloat cexp_fast(float a, float b, float m) {
    const float INV2PI = 0.15915494309189535f;
    const float C1     = 6.28125f;                  // exact in fp32
    const float C2     = 1.9353071795864764e-3f;    // 2*pi - C1
    float am = a * m;
    float bm = b * m;
    float k  = rintf(bm * INV2PI);
    float r  = fmaf(-k, C1, bm);
    r        = fmaf(-k, C2, r);
    float s, c;
    __sincosf(r, &s, &c);
    float e = __expf(am);
    cfloat o; o.r = e * c; o.i = e * s;
    return o;
}

// ---------------- pre-kernel: one thread per table entry ----------------
__global__ __launch_bounds__(256)
void pmsn_pre(const float* __restrict__ log_dt,
              const float* __restrict__ log_A_real,
              const float* __restrict__ A_imag,
              const float* __restrict__ VinvB_real,
              const float* __restrict__ VinvB_imag,
              const float* __restrict__ CV_real,
              const float* __restrict__ CV_imag,
              int H)
{
    const int jid  = blockIdx.x * blockDim.x + threadIdx.x;
    const int njob = H * 2 * 27;
    if (jid >= njob) return;

    const int e  = jid % 27;
    const int hs = jid / 27;
    const int s  = hs & 1;
    const int h  = hs >> 1;

    // pick the s-th state with positive imaginary part
    const int base = h * NSTATE;
    int n = 0, seen = 0;
#pragma unroll
    for (int m = 0; m < NSTATE; ++m) {
        if (A_imag[base + m] > 0.0f) {
            if (seen == s) n = m;
            ++seen;
        }
    }
    const int idx = base + n;

    const float dt  = __expf(log_dt[h]);
    const float Aim = A_imag[idx];
    const float Are = -__expf(log_A_real[idx]);
    const float a = Are * dt;
    const float b = Aim * dt;

    cfloat v;
    if (e < 16) {
        v = cexp_fast(a, b, (float)(32 * e));
    } else if (e < 24) {
        v = cexp_fast(a, b, (float)(4 * (e - 16)));
    } else if (e == 24) {
        v = cexp_fast(a, b, 1.0f);
    } else if (e == 25) {
        v = cexp_fast(a, b, (float)STRIDE);
    } else {
        // coeff = 2 * C * B_bar,  B_bar = (A_bar - 1) * B / A
        const cfloat Ab = cexp_fast(a, b, 1.0f);
        const float Br = VinvB_real[idx], Bi = VinvB_imag[idx];
        const float t1r = (Ab.r - 1.0f) * Br - Ab.i * Bi;
        const float t1i = (Ab.r - 1.0f) * Bi + Ab.i * Br;
        const float invA = 1.0f / (Are * Are + Aim * Aim);
        const float Bbr = (t1r * Are + t1i * Aim) * invA;
        const float Bbi = (t1i * Are - t1r * Aim) * invA;
        const float Cr = CV_real[idx], Ci = CV_imag[idx];
        v.r = 2.0f * (Cr * Bbr - Ci * Bbi);
        v.i = 2.0f * (Cr * Bbi + Ci * Bbr);
    }

    g_tab[hs * TABN + e] = make_float2(v.r, v.i);
}

// ---------------- main kernel: setup-free ----------------
__global__ __launch_bounds__(TPB, 12)
void pmsn_main(float* __restrict__ out, int L)
{
    const int h   = blockIdx.x;
    const int tid = threadIdx.x;
    const int j4  = tid >> 3;           // 4*tid = 32*j + 4*i
    const int i4  = tid & 7;

    float ua[2][4], ub[2][4], p[2], q[2];

#pragma unroll
    for (int s = 0; s < 2; ++s) {
        const float2* tb = &g_tab[(h * 2 + s) * TABN];
        const float2 P32f = tb[j4];
        const float2 P4f  = tb[16 + i4];
        const float2 Abf  = tb[24];
        const float2 Wf   = tb[25];
        const float2 cff  = tb[26];

        cfloat P32; P32.r = P32f.x; P32.i = P32f.y;
        cfloat P4;  P4.r  = P4f.x;  P4.i  = P4f.y;
        cfloat Ab;  Ab.r  = Abf.x;  Ab.i  = Abf.y;
        cfloat W;   W.r   = Wf.x;   W.i   = Wf.y;
        cfloat cf;  cf.r  = cff.x;  cf.i  = cff.y;

        cfloat z = cmul(cmul(cf, P32), P4);
#pragma unroll
        for (int o = 0; o < 4; ++o) {
            if (o > 0) z = cmul(z, Ab);
            ua[s][o] = z.r;
            ub[s][o] = fmaf(z.r, W.r, -z.i * W.i);
        }
        p[s] = 2.0f * W.r;
        q[s] = -fmaf(W.r, W.r, W.i * W.i);
    }

    float* rowp = out + (size_t)h * (size_t)L + 4 * tid;
    const int niter = L / STRIDE;

    if (niter * STRIDE == L) {
#pragma unroll 8
        for (int k = 0; k < niter; ++k) {
            float4 v;
            v.x = ua[0][0] + ua[1][0];
            v.y = ua[0][1] + ua[1][1];
            v.z = ua[0][2] + ua[1][2];
            v.w = ua[0][3] + ua[1][3];
            *reinterpret_cast<float4*>(rowp) = v;
            rowp += STRIDE;
#pragma unroll
            for (int s = 0; s < 2; ++s)
#pragma unroll
                for (int o = 0; o < 4; ++o) {
                    const float x = fmaf(p[s], ub[s][o], q[s] * ua[s][o]);
                    ua[s][o] = ub[s][o];
                    ub[s][o] = x;
                }
        }
    } else {
        for (int l = 4 * tid; l < L; l += STRIDE) {
            float vv[4];
#pragma unroll
            for (int o = 0; o < 4; ++o) vv[o] = ua[0][o] + ua[1][o];
            if (l + 4 <= L) {
                *reinterpret_cast<float4*>(rowp) =
                    make_float4(vv[0], vv[1], vv[2], vv[3]);
            } else {
                for (int o = 0; o < 4 && l + o < L; ++o) rowp[o] = vv[o];
            }
            rowp += STRIDE;
#pragma unroll
            for (int s = 0; s < 2; ++s)
#pragma unroll
                for (int o = 0; o < 4; ++o) {
                    const float x = fmaf(p[s], ub[s][o], q[s] * ua[s][o]);
                    ua[s][o] = ub[s][o];
                    ub[s][o] = x;
                }
        }
    }
}

extern "C" void kernel_launch(void* const* d_in, const int* in_sizes, int n_in,
                              void* d_out, int out_size)
{
    const float* log_dt     = (const float*)d_in[0];
    const float* log_A_real = (const float*)d_in[1];
    const float* A_imag     = (const float*)d_in[2];
    const float* VinvB_real = (const float*)d_in[3];
    const float* VinvB_imag = (const float*)d_in[4];
    const float* CV_real    = (const float*)d_in[5];
    const float* CV_imag    = (const float*)d_in[6];

    const int H = in_sizes[0];
    const int L = out_size / H;

    float* out = (float*)d_out;

    const int njob = H * 2 * 27;
    pmsn_pre<<<(njob + 255) / 256, 256>>>(log_dt, log_A_real, A_imag,
                                          VinvB_real, VinvB_imag,
                                          CV_real, CV_imag, H);
    pmsn_main<<<H, TPB>>>(out, L);
}

// round 16
// speedup vs baseline: 1.2442x; 1.1831x over previous
#include <cuda_runtime.h>
#include <cuda_bf16.h>
#include <math.h>

// PMSN / S4D:  out[h,l] = Re( sum_n coeff_{h,n} * A_bar_{h,n}^l )
//
// R16 = R12 (single kernel, smem table, conjugate-pair reduced, 8 order-2
// real recurrence chains, STG.128) with a compressed critical path:
//   - branchless setup: 29 jobs/state on lanes {0-28 | 32-60}, one predicated
//     select for the exponent m, single uniform MUFU cexp path
//   - table adds A_bar^2, A_bar^3 -> seed offsets z*Ab^o are parallel
//   - __ldg prefetch of all params before any arithmetic
//   - fully unrolled niter==8 fast path (no loop overhead)

#define NSTATE 4
#define ACT    2
#define TPB    128
#define STRIDE (4 * TPB)     // 512

struct __align__(8) cfloat { float r, i; };

__device__ __forceinline__ cfloat cmul(cfloat a, cfloat b) {
    cfloat o;
    o.r = fmaf(a.r, b.r, -a.i * b.i);
    o.i = fmaf(a.r, b.i,  a.i * b.r);
    return o;
}

// exp((a + i b) * m). MUFU + fp32 Cody-Waite phase reduction.
__device__ __forceinline__ cfloat cexp_fast(float a, float b, float m) {
    const float INV2PI = 0.15915494309189535f;
    const float C1     = 6.28125f;                  // exact in fp32
    const float C2     = 1.9353071795864764e-3f;    // 2*pi - C1
    float am = a * m;
    float bm = b * m;
    float k  = rintf(bm * INV2PI);
    float r  = fmaf(-k, C1, bm);
    r        = fmaf(-k, C2, r);
    float s, c;
    __sincosf(r, &s, &c);
    float e = __expf(am);
    cfloat o; o.r = e * c; o.i = e * s;
    return o;
}

// table layout per state: [0..15]=P32[j]=A_bar^(32j), [16..23]=P4[i]=A_bar^(4i),
// [24]=Ab, [25]=Ab^2, [26]=Ab^3, [27]=W=A_bar^512, [28]=coeff
#define TABN 29

__global__ __launch_bounds__(TPB, 16)
void pmsn_kernel(const float* __restrict__ log_dt,
                 const float* __restrict__ log_A_real,
                 const float* __restrict__ A_imag,
                 const float* __restrict__ VinvB_real,
                 const float* __restrict__ VinvB_imag,
                 const float* __restrict__ CV_real,
                 const float* __restrict__ CV_imag,
                 float* __restrict__ out,
                 int L)
{
    __shared__ cfloat sTab[ACT][TABN];

    const int h   = blockIdx.x;
    const int tid = threadIdx.x;

    // ---- setup: lanes {0..28, 32..60}, branchless job selection ----
    if (tid < 64) {
        const int s = tid >> 5;             // state slot 0/1
        const int r = tid & 31;             // job id
        const int base = h * NSTATE;

        // prefetch everything up front (overlap latency with MUFU below)
        const float im0 = __ldg(A_imag + base + 0);
        const float im1 = __ldg(A_imag + base + 1);
        const float im2 = __ldg(A_imag + base + 2);
        const float im3 = __ldg(A_imag + base + 3);
        const float ldt = __ldg(log_dt + h);

        if (r < TABN) {
            // pick the s-th state with positive imaginary part
            int n = 0, seen = 0;
            if (im0 > 0.0f) { if (seen == s) n = 0; ++seen; }
            if (im1 > 0.0f) { if (seen == s) n = 1; ++seen; }
            if (im2 > 0.0f) { if (seen == s) n = 2; ++seen; }
            if (im3 > 0.0f) { if (seen == s) n = 3; ++seen; }
            const int idx = base + n;

            const float Aim = (n == 0) ? im0 : (n == 1) ? im1 : (n == 2) ? im2 : im3;
            const float dt  = __expf(ldt);
            const float Are = -__expf(__ldg(log_A_real + idx));
            const float a = Are * dt;
            const float b = Aim * dt;

            // branchless exponent select
            float m;
            if      (r < 16) m = (float)(32 * r);
            else if (r < 24) m = (float)(4 * (r - 16));
            else if (r == 24) m = 1.0f;
            else if (r == 25) m = 2.0f;
            else if (r == 26) m = 3.0f;
            else if (r == 27) m = (float)STRIDE;
            else              m = 1.0f;              // coeff lane uses Ab

            cfloat v = cexp_fast(a, b, m);

            if (r == 28) {
                // coeff = 2 * C * B_bar,  B_bar = (A_bar - 1) * B / A
                const cfloat Ab = v;
                const float Br = __ldg(VinvB_real + idx), Bi = __ldg(VinvB_imag + idx);
                const float t1r = (Ab.r - 1.0f) * Br - Ab.i * Bi;
                const float t1i = (Ab.r - 1.0f) * Bi + Ab.i * Br;
                const float invA = 1.0f / (Are * Are + Aim * Aim);
                const float Bbr = (t1r * Are + t1i * Aim) * invA;
                const float Bbi = (t1i * Are - t1r * Aim) * invA;
                const float Cr = __ldg(CV_real + idx), Ci = __ldg(CV_imag + idx);
                v.r = 2.0f * (Cr * Bbr - Ci * Bbi);
                v.i = 2.0f * (Cr * Bbi + Ci * Bbr);
            }

            sTab[s][r] = v;
        }
    }
    __syncthreads();

    // ---- seeds: z_o = coeff * A_bar^(4*tid) * Ab^o, o=0..3 (parallel) ----
    float ua[ACT][4], ub[ACT][4], p[ACT], q[ACT];
    const int j4 = tid >> 3;                // 4*tid = 32*j + 4*i
    const int i4 = tid & 7;

#pragma unroll
    for (int s = 0; s < ACT; ++s) {
        const cfloat W   = sTab[s][27];
        const cfloat cf  = sTab[s][28];
        const cfloat z0  = cmul(cmul(cf, sTab[s][j4]), sTab[s][16 + i4]);
        const cfloat z1  = cmul(z0, sTab[s][24]);
        const cfloat z2  = cmul(z0, sTab[s][25]);
        const cfloat z3  = cmul(z0, sTab[s][26]);

        ua[s][0] = z0.r;  ub[s][0] = fmaf(z0.r, W.r, -z0.i * W.i);
        ua[s][1] = z1.r;  ub[s][1] = fmaf(z1.r, W.r, -z1.i * W.i);
        ua[s][2] = z2.r;  ub[s][2] = fmaf(z2.r, W.r, -z2.i * W.i);
        ua[s][3] = z3.r;  ub[s][3] = fmaf(z3.r, W.r, -z3.i * W.i);

        p[s] = 2.0f * W.r;
        q[s] = -fmaf(W.r, W.r, W.i * W.i);
    }

    // ---- main loop: 8 chains, STG.128 ----
    float* rowp = out + (size_t)h * (size_t)L + 4 * tid;

    if (L == 8 * STRIDE) {
        // fully unrolled fast path (L = 4096)
#pragma unroll
        for (int k = 0; k < 8; ++k) {
            float4 v;
            v.x = ua[0][0] + ua[1][0];
            v.y = ua[0][1] + ua[1][1];
            v.z = ua[0][2] + ua[1][2];
            v.w = ua[0][3] + ua[1][3];
            *reinterpret_cast<float4*>(rowp) = v;
            rowp += STRIDE;
#pragma unroll
            for (int s = 0; s < ACT; ++s)
#pragma unroll
                for (int o = 0; o < 4; ++o) {
                    const float x = fmaf(p[s], ub[s][o], q[s] * ua[s][o]);
                    ua[s][o] = ub[s][o];
                    ub[s][o] = x;
                }
        }
    } else {
        for (int l = 4 * tid; l < L; l += STRIDE) {
            float vv[4];
#pragma unroll
            for (int o = 0; o < 4; ++o) vv[o] = ua[0][o] + ua[1][o];
            if (l + 4 <= L) {
                *reinterpret_cast<float4*>(rowp) =
                    make_float4(vv[0], vv[1], vv[2], vv[3]);
            } else {
                for (int o = 0; o < 4 && l + o < L; ++o) rowp[o] = vv[o];
            }
            rowp += STRIDE;
#pragma unroll
            for (int s = 0; s < ACT; ++s)
#pragma unroll
                for (int o = 0; o < 4; ++o) {
                    const float x = fmaf(p[s], ub[s][o], q[s] * ua[s][o]);
                    ua[s][o] = ub[s][o];
                    ub[s][o] = x;
                }
        }
    }
}

extern "C" void kernel_launch(void* const* d_in, const int* in_sizes, int n_in,
                              void* d_out, int out_size)
{
    const float* log_dt     = (const float*)d_in[0];
    const float* log_A_real = (const float*)d_in[1];
    const float* A_imag     = (const float*)d_in[2];
    const float* VinvB_real = (const float*)d_in[3];
    const float* VinvB_imag = (const float*)d_in[4];
    const float* CV_real    = (const float*)d_in[5];
    const float* CV_imag    = (const float*)d_in[6];

    const int H = in_sizes[0];
    const int L = out_size / H;

    float* out = (float*)d_out;

    pmsn_kernel<<<H, TPB>>>(log_dt, log_A_real, A_imag,
                            VinvB_real, VinvB_imag,
                            CV_real, CV_imag, out, L);
}